// round 13
// baseline (speedup 1.0000x reference)
#include <cuda_runtime.h>

#define NQ 25
#define KVD 9
#define ROW 225
#define WPB 4              // warps per block
#define SPW 2              // samples per warp
#define SPB (WPB*SPW)      // 8
#define THREADS (WPB*32)   // 128
#define RSTRIDE 16         // u64 per merged K|V|Q row (128B)
#define SSTRIDE (NQ*RSTRIDE + 2)   // u64 per sample (+16B bank skew)

typedef unsigned long long u64;

__device__ __forceinline__ u64 pk(float lo, float hi) {
    u64 r; asm("mov.b64 %0,{%1,%2};" : "=l"(r) : "f"(lo), "f"(hi)); return r;
}
__device__ __forceinline__ void unpk(u64 v, float& lo, float& hi) {
    asm("mov.b64 {%0,%1},%2;" : "=f"(lo), "=f"(hi) : "l"(v));
}
__device__ __forceinline__ u64 fma2(u64 a, u64 b, u64 c) {
    u64 d; asm("fma.rn.f32x2 %0,%1,%2,%3;" : "=l"(d) : "l"(a), "l"(b), "l"(c)); return d;
}
__device__ __forceinline__ u64 mul2(u64 a, u64 b) {
    u64 d; asm("mul.rn.f32x2 %0,%1,%2;" : "=l"(d) : "l"(a), "l"(b)); return d;
}
__device__ __forceinline__ u64 add2(u64 a, u64 b) {
    u64 d; asm("add.rn.f32x2 %0,%1,%2;" : "=l"(d) : "l"(a), "l"(b)); return d;
}

// Merged row layout (u64 idx):
//  [0]=(k0,k1) [1]=(k2,k3) [2]=(k4,k5) [3]=(k6,k7) [4]=(k8, mask*-1e9)
//  [5]=(v0,v1) [6]=(v2,v3) [7]=(v4,v5) [8]=(v6,v7) [9]=(v8, 0)
//  [10..13]=q pairs, [14]=(q8, 1)  [15]=pad

__global__ __launch_bounds__(THREADS, 5)
void attn_fused_kernel(
    const float* __restrict__ x,     const float* __restrict__ mask,
    const float* __restrict__ Wq,    const float* __restrict__ bq,
    const float* __restrict__ Wk,    const float* __restrict__ bk,
    const float* __restrict__ Wv,    const float* __restrict__ bv,
    const float* __restrict__ gamma, const float* __restrict__ beta,
    float* __restrict__ out, int B)
{
    __shared__ alignas(16) u64 sW[3][4][KVD][6];
    __shared__ alignas(16) u64 sB[3][4][6];
    __shared__ alignas(16) u64 sG[6], sBt[6];
    __shared__ float sMaskF[32];
    __shared__ alignas(16) u64 sKV[WPB][SPW * SSTRIDE];
    __shared__ float sX[WPB][SPW][ROW];   // coalesced in/out staging

    const int tid  = threadIdx.x;
    const int warp = tid >> 5;
    const int lane = tid & 31;

    // ---- repack constants (Wq,bq pre-scaled 1/3; q aug = 1, k aug = mask*-1e9) ----
    for (int i = tid; i < 540; i += THREADS) {
        const int p  = i % 5;
        const int d  = (i / 5) % KVD;
        const int g  = (i / 45) % 4;
        const int pr = i / 180;
        const float* W = (pr == 0) ? Wq : (pr == 1) ? Wk : Wv;
        const float sc = (pr == 0) ? (1.0f / 3.0f) : 1.0f;
        const int e = 2 * p;
        const float lo = W[g * 81 + e * KVD + d] * sc;
        const float hi = (e + 1 < KVD) ? W[g * 81 + (e + 1) * KVD + d] * sc : 0.f;
        sW[pr][g][d][p] = pk(lo, hi);
    }
    for (int i = tid; i < 60; i += THREADS) {
        const int p  = i % 5;
        const int g  = (i / 5) % 4;
        const int pr = i / 20;
        const float* Bb = (pr == 0) ? bq : (pr == 1) ? bk : bv;
        const float sc = (pr == 0) ? (1.0f / 3.0f) : 1.0f;
        const int e = 2 * p;
        const float lo = Bb[g * KVD + e] * sc;
        float hi;
        if (e + 1 < KVD) hi = Bb[g * KVD + e + 1] * sc;
        else             hi = (pr == 0) ? 1.0f : 0.0f;
        sB[pr][g][p] = pk(lo, hi);
    }
    if (tid < 5) {
        const int e = 2 * tid;
        sG[tid]  = pk(gamma[e], (e + 1 < KVD) ? gamma[e + 1] : 0.f);
        sBt[tid] = pk(beta[e],  (e + 1 < KVD) ? beta[e + 1]  : 0.f);
    }
    if (tid < NQ) sMaskF[tid] = mask[tid] * -1e9f;
    __syncthreads();

    const long s0 = (long)blockIdx.x * SPB + warp * SPW;
    const bool vA = (s0 < (long)B);
    const bool vB = (s0 + 1 < (long)B);

    // ---- coalesced input staging ----
    float* sxA = &sX[warp][0][0];
    float* sxB = &sX[warp][1][0];
    if (vB) {
        const float* xrow = x + s0 * ROW;
        #pragma unroll
        for (int i = lane; i < 2 * ROW; i += 32) sxA[i] = xrow[i];
    } else if (vA) {
        const float* xrow = x + s0 * ROW;
        #pragma unroll
        for (int i = lane; i < ROW; i += 32) sxA[i] = xrow[i];
    }
    __syncwarp();

    // ---- phase 1: lane = item; project Q,K,V for both samples ----
    if (lane < NQ) {
        const int g = (lane < 3) ? 0 : (lane < 13) ? 1 : (lane < 23) ? 2 : 3;
        float xa[KVD], xb[KVD];
        #pragma unroll
        for (int d = 0; d < KVD; d++) {
            xa[d] = sxA[lane * KVD + d];
            xb[d] = sxB[lane * KVD + d];
        }
        const float mterm = sMaskF[lane];
        u64* ra = &sKV[warp][0 * SSTRIDE + lane * RSTRIDE];
        u64* rb = &sKV[warp][1 * SSTRIDE + lane * RSTRIDE];

        #pragma unroll
        for (int pr = 0; pr < 3; pr++) {   // 0=Q 1=K 2=V, one at a time (reg lean)
            u64 aA[5], aB[5];
            #pragma unroll
            for (int p = 0; p < 5; p++) { aA[p] = sB[pr][g][p]; aB[p] = aA[p]; }
            #pragma unroll
            for (int d = 0; d < KVD; d++) {
                const u64 x0 = pk(xa[d], xa[d]);
                const u64 x1 = pk(xb[d], xb[d]);
                const u64* w = &sW[pr][g][d][0];
                const ulonglong2 w01 = *(const ulonglong2*)w;
                const ulonglong2 w23 = *(const ulonglong2*)(w + 2);
                const u64 w4 = w[4];
                aA[0]=fma2(x0,w01.x,aA[0]); aA[1]=fma2(x0,w01.y,aA[1]);
                aA[2]=fma2(x0,w23.x,aA[2]); aA[3]=fma2(x0,w23.y,aA[3]);
                aA[4]=fma2(x0,w4,   aA[4]);
                aB[0]=fma2(x1,w01.x,aB[0]); aB[1]=fma2(x1,w01.y,aB[1]);
                aB[2]=fma2(x1,w23.x,aB[2]); aB[3]=fma2(x1,w23.y,aB[3]);
                aB[4]=fma2(x1,w4,   aB[4]);
            }
            if (pr == 0) {                       // Q at [10..14]
                *(ulonglong2*)(ra + 10) = make_ulonglong2(aA[0], aA[1]);
                *(ulonglong2*)(ra + 12) = make_ulonglong2(aA[2], aA[3]);
                ra[14] = aA[4];
                *(ulonglong2*)(rb + 10) = make_ulonglong2(aB[0], aB[1]);
                *(ulonglong2*)(rb + 12) = make_ulonglong2(aB[2], aB[3]);
                rb[14] = aB[4];
            } else if (pr == 1) {                // K at [0..4], aug hi = mterm
                float lo, hi;
                *(ulonglong2*)(ra + 0) = make_ulonglong2(aA[0], aA[1]);
                *(ulonglong2*)(ra + 2) = make_ulonglong2(aA[2], aA[3]);
                unpk(aA[4], lo, hi); ra[4] = pk(lo, mterm);
                *(ulonglong2*)(rb + 0) = make_ulonglong2(aB[0], aB[1]);
                *(ulonglong2*)(rb + 2) = make_ulonglong2(aB[2], aB[3]);
                unpk(aB[4], lo, hi); rb[4] = pk(lo, mterm);
            } else {                             // V at [5..9] (5 is 8B-aligned: scalar)
                ra[5] = aA[0];
                *(ulonglong2*)(ra + 6) = make_ulonglong2(aA[1], aA[2]);
                *(ulonglong2*)(ra + 8) = make_ulonglong2(aA[3], aA[4]);
                rb[5] = aB[0];
                *(ulonglong2*)(rb + 6) = make_ulonglong2(aB[1], aB[2]);
                *(ulonglong2*)(rb + 8) = make_ulonglong2(aB[3], aB[4]);
            }
        }
    }
    __syncwarp();

    // ---- phase 2: 26 lanes = 2 samples x 13 lanes; 2 q-rows per lane ----
    if (lane < 26) {
        const int sel  = (lane >= 13) ? 1 : 0;
        const int idx  = lane - 13 * sel;
        const int r0   = 2 * idx;
        const bool has1 = (2 * idx + 1 < NQ);
        const int r1   = has1 ? (2 * idx + 1) : (NQ - 1);

        const u64* sbase = &sKV[warp][sel * SSTRIDE];

        u64 q[2][5];
        #pragma unroll
        for (int s = 0; s < 2; s++) {
            const u64* r = sbase + ((s == 0) ? r0 : r1) * RSTRIDE;
            const ulonglong2 q01 = *(const ulonglong2*)(r + 10);
            const ulonglong2 q23 = *(const ulonglong2*)(r + 12);
            q[s][0] = q01.x; q[s][1] = q01.y;
            q[s][2] = q23.x; q[s][3] = q23.y;
            q[s][4] = r[14];
        }

        u64 o[2][5];
        float sum[2] = {0.f, 0.f};
        #pragma unroll
        for (int s = 0; s < 2; s++)
            #pragma unroll
            for (int p = 0; p < 5; p++) o[s][p] = 0;

        #pragma unroll
        for (int j = 0; j < NQ; j++) {
            const u64* r = sbase + j * RSTRIDE;
            const ulonglong2 L0 = *(const ulonglong2*)(r + 0);  // (k0k1)(k2k3)
            const ulonglong2 L1 = *(const ulonglong2*)(r + 2);  // (k4k5)(k6k7)
            const ulonglong2 L2 = *(const ulonglong2*)(r + 4);  // (k8,m)(v0v1)
            const ulonglong2 L3 = *(const ulonglong2*)(r + 6);  // (v2v3)(v4v5)
            const ulonglong2 L4 = *(const ulonglong2*)(r + 8);  // (v6v7)(v8,0)
            u64 ep[2];
            #pragma unroll
            for (int s = 0; s < 2; s++) {
                u64 acc = mul2(q[s][0], L0.x);
                acc = fma2(q[s][1], L0.y, acc);
                acc = fma2(q[s][2], L1.x, acc);
                acc = fma2(q[s][3], L1.y, acc);
                acc = fma2(q[s][4], L2.x, acc);
                float lo, hi; unpk(acc, lo, hi);
                const float e = __expf(lo + hi);
                sum[s] += e;
                ep[s] = pk(e, e);
            }
            #pragma unroll
            for (int s = 0; s < 2; s++) {
                o[s][0] = fma2(ep[s], L2.y, o[s][0]);
                o[s][1] = fma2(ep[s], L3.x, o[s][1]);
                o[s][2] = fma2(ep[s], L3.y, o[s][2]);
                o[s][3] = fma2(ep[s], L4.x, o[s][3]);
                o[s][4] = fma2(ep[s], L4.y, o[s][4]);
            }
        }

        // ---- epilogue per q-row: normalize + residual + layernorm → sX ----
        const u64 g01 = sG[0], g1p = sG[1], g2p = sG[2], g3p = sG[3];
        const u64 b01 = sBt[0], b1p = sBt[1], b2p = sBt[2], b3p = sBt[3];
        float g8, b8, zz;
        unpk(sG[4], g8, zz); unpk(sBt[4], b8, zz);
        float* sxS = (sel == 0) ? sxA : sxB;
        #pragma unroll
        for (int s = 0; s < 2; s++) {
            if (s == 1 && !has1) break;      // clamped duplicate row
            const int row = (s == 0) ? r0 : r1;
            float xr[KVD];
            #pragma unroll
            for (int d = 0; d < KVD; d++) xr[d] = sxS[row * KVD + d];

            const float inv = 1.0f / sum[s];
            const u64 inv2 = pk(inv, inv);
            const u64 f0 = fma2(o[s][0], inv2, pk(xr[0], xr[1]));
            const u64 f1 = fma2(o[s][1], inv2, pk(xr[2], xr[3]));
            const u64 f2 = fma2(o[s][2], inv2, pk(xr[4], xr[5]));
            const u64 f3 = fma2(o[s][3], inv2, pk(xr[6], xr[7]));
            const u64 f4 = fma2(o[s][4], inv2, pk(xr[8], 0.f));

            float e0,e1,e2,e3,e4,e5,e6,e7,e8,ez;
            unpk(f0, e0, e1); unpk(f1, e2, e3);
            unpk(f2, e4, e5); unpk(f3, e6, e7);
            unpk(f4, e8, ez);
            const float mu = (e0+e1+e2+e3+e4+e5+e6+e7+e8) * (1.0f/9.0f);
            const u64 nmu2 = pk(-mu, -mu);
            const u64 t0 = add2(f0, nmu2);
            const u64 t1 = add2(f1, nmu2);
            const u64 t2 = add2(f2, nmu2);
            const u64 t3 = add2(f3, nmu2);
            const float t8 = e8 - mu;
            u64 vacc = mul2(t0, t0);
            vacc = fma2(t1, t1, vacc);
            vacc = fma2(t2, t2, vacc);
            vacc = fma2(t3, t3, vacc);
            float va0, va1; unpk(vacc, va0, va1);
            const float var = (va0 + va1 + t8 * t8) * (1.0f/9.0f);
            const float rinv = rsqrtf(var + 1e-5f);
            const u64 rinv2 = pk(rinv, rinv);

            const u64 r0p = fma2(mul2(t0, rinv2), g01, b01);
            const u64 r1p = fma2(mul2(t1, rinv2), g1p, b1p);
            const u64 r2p = fma2(mul2(t2, rinv2), g2p, b2p);
            const u64 r3p = fma2(mul2(t3, rinv2), g3p, b3p);
            const float r8v = t8 * rinv * g8 + b8;

            float w0,w1,w2,w3,w4,w5,w6,w7;
            unpk(r0p,w0,w1); unpk(r1p,w2,w3); unpk(r2p,w4,w5); unpk(r3p,w6,w7);
            float* so = sxS + row * KVD;
            so[0]=w0; so[1]=w1; so[2]=w2; so[3]=w3;
            so[4]=w4; so[5]=w5; so[6]=w6; so[7]=w7; so[8]=r8v;
        }
    }
    __syncwarp();

    // ---- coalesced output ----
    if (vB) {
        float* orow = out + s0 * ROW;
        #pragma unroll
        for (int i = lane; i < 2 * ROW; i += 32) orow[i] = sxA[i];
    } else if (vA) {
        float* orow = out + s0 * ROW;
        #pragma unroll
        for (int i = lane; i < ROW; i += 32) orow[i] = sxA[i];
    }
}

extern "C" void kernel_launch(void* const* d_in, const int* in_sizes, int n_in,
                              void* d_out, int out_size)
{
    const float* x     = (const float*)d_in[0];
    const float* mask  = (const float*)d_in[1];
    const float* Wq    = (const float*)d_in[2];
    const float* bq    = (const float*)d_in[3];
    const float* Wk    = (const float*)d_in[4];
    const float* bk    = (const float*)d_in[5];
    const float* Wv    = (const float*)d_in[6];
    const float* bv    = (const float*)d_in[7];
    const float* gamma = (const float*)d_in[8];
    const float* beta  = (const float*)d_in[9];
    float* out = (float*)d_out;

    const int B = in_sizes[0] / ROW;
    const int blocks = (B + SPB - 1) / SPB;
    attn_fused_kernel<<<blocks, THREADS>>>(x, mask, Wq, bq, Wk, bk, Wv, bv,
                                           gamma, beta, out, B);
}

// round 14
// speedup vs baseline: 1.4377x; 1.4377x over previous
#include <cuda_runtime.h>

#define NQ 25
#define KVD 9
#define ROW 225
#define WPB 3              // warps per block
#define SPW 3              // samples per warp
#define SPB (WPB*SPW)      // 9 samples per block
#define THREADS (WPB*32)   // 96
#define RSTRIDE 18         // u64 per merged K|V|Q row (144B: 16 mod 128 -> 8 bank offsets)

typedef unsigned long long u64;

__device__ __forceinline__ u64 pk(float lo, float hi) {
    u64 r; asm("mov.b64 %0,{%1,%2};" : "=l"(r) : "f"(lo), "f"(hi)); return r;
}
__device__ __forceinline__ void unpk(u64 v, float& lo, float& hi) {
    asm("mov.b64 {%0,%1},%2;" : "=f"(lo), "=f"(hi) : "l"(v));
}
__device__ __forceinline__ u64 fma2(u64 a, u64 b, u64 c) {
    u64 d; asm("fma.rn.f32x2 %0,%1,%2,%3;" : "=l"(d) : "l"(a), "l"(b), "l"(c)); return d;
}
__device__ __forceinline__ u64 mul2(u64 a, u64 b) {
    u64 d; asm("mul.rn.f32x2 %0,%1,%2;" : "=l"(d) : "l"(a), "l"(b)); return d;
}
__device__ __forceinline__ u64 add2(u64 a, u64 b) {
    u64 d; asm("add.rn.f32x2 %0,%1,%2;" : "=l"(d) : "l"(a), "l"(b)); return d;
}

// Merged row layout (u64 idx):
//  [0]=(k0,k1) [1]=(k2,k3) [2]=(k4,k5) [3]=(k6,k7) [4]=(k8, mask*-1e9)
//  [5]=(v0,v1) [6]=(v2,v3) [7]=(v4,v5) [8]=(v6,v7) [9]=(v8, 0)
//  [10..13]=q pairs, [14]=(q8, 1)  [15..17]=pad (row stride 144B)

__global__ __launch_bounds__(THREADS, 4)
void attn_fused_kernel(
    const float* __restrict__ x,     const float* __restrict__ mask,
    const float* __restrict__ Wq,    const float* __restrict__ bq,
    const float* __restrict__ Wk,    const float* __restrict__ bk,
    const float* __restrict__ Wv,    const float* __restrict__ bv,
    const float* __restrict__ gamma, const float* __restrict__ beta,
    float* __restrict__ out, int B)
{
    __shared__ alignas(16) u64 sW[3][4][KVD][6];
    __shared__ alignas(16) u64 sB[3][4][6];
    __shared__ alignas(16) u64 sG[6], sBt[6];
    __shared__ float sMaskF[32];
    __shared__ alignas(16) u64 sKV[WPB][SPW][NQ][RSTRIDE];
    __shared__ float sX[WPB][SPW][ROW];

    const int tid  = threadIdx.x;
    const int warp = tid >> 5;
    const int lane = tid & 31;

    // ---- repack constants (Wq,bq pre-scaled 1/3; q aug = 1, k aug = mask*-1e9) ----
    for (int i = tid; i < 540; i += THREADS) {
        const int p  = i % 5;
        const int d  = (i / 5) % KVD;
        const int g  = (i / 45) % 4;
        const int pr = i / 180;
        const float* W = (pr == 0) ? Wq : (pr == 1) ? Wk : Wv;
        const float sc = (pr == 0) ? (1.0f / 3.0f) : 1.0f;
        const int e = 2 * p;
        const float lo = W[g * 81 + e * KVD + d] * sc;
        const float hi = (e + 1 < KVD) ? W[g * 81 + (e + 1) * KVD + d] * sc : 0.f;
        sW[pr][g][d][p] = pk(lo, hi);
    }
    for (int i = tid; i < 60; i += THREADS) {
        const int p  = i % 5;
        const int g  = (i / 5) % 4;
        const int pr = i / 20;
        const float* Bb = (pr == 0) ? bq : (pr == 1) ? bk : bv;
        const float sc = (pr == 0) ? (1.0f / 3.0f) : 1.0f;
        const int e = 2 * p;
        const float lo = Bb[g * KVD + e] * sc;
        float hi;
        if (e + 1 < KVD) hi = Bb[g * KVD + e + 1] * sc;
        else             hi = (pr == 0) ? 1.0f : 0.0f;
        sB[pr][g][p] = pk(lo, hi);
    }
    if (tid < 5) {
        const int e = 2 * tid;
        sG[tid]  = pk(gamma[e], (e + 1 < KVD) ? gamma[e + 1] : 0.f);
        sBt[tid] = pk(beta[e],  (e + 1 < KVD) ? beta[e + 1]  : 0.f);
    }
    if (tid < NQ) sMaskF[tid] = mask[tid] * -1e9f;
    __syncthreads();

    const long s0 = (long)blockIdx.x * SPB + warp * SPW;
    long nrem = (long)B - s0;
    const int cnt = (nrem <= 0) ? 0 : (nrem >= SPW ? SPW : (int)nrem);

    // ---- coalesced input staging ----
    float* sxAll = &sX[warp][0][0];
    {
        const float* xrow = x + s0 * ROW;
        const int total = cnt * ROW;
        for (int i = lane; i < total; i += 32) sxAll[i] = xrow[i];
    }
    __syncwarp();

    // ---- phase 1: lane = item; 3 samples; one projection at a time ----
    if (lane < NQ) {
        const int g = (lane < 3) ? 0 : (lane < 13) ? 1 : (lane < 23) ? 2 : 3;
        float xv[SPW][KVD];
        #pragma unroll
        for (int s = 0; s < SPW; s++)
            #pragma unroll
            for (int d = 0; d < KVD; d++) xv[s][d] = sX[warp][s][lane * KVD + d];
        const float mterm = sMaskF[lane];

        u64* r0 = &sKV[warp][0][lane][0];
        u64* r1 = &sKV[warp][1][lane][0];
        u64* r2 = &sKV[warp][2][lane][0];

        #pragma unroll
        for (int pr = 0; pr < 3; pr++) {     // 0=Q 1=K 2=V
            u64 acc[SPW][5];
            #pragma unroll
            for (int s = 0; s < SPW; s++)
                #pragma unroll
                for (int p = 0; p < 5; p++) acc[s][p] = sB[pr][g][p];

            #pragma unroll
            for (int d = 0; d < KVD; d++) {
                const u64* w = &sW[pr][g][d][0];
                const ulonglong2 w01 = *(const ulonglong2*)w;
                const ulonglong2 w23 = *(const ulonglong2*)(w + 2);
                const u64 w4 = w[4];
                #pragma unroll
                for (int s = 0; s < SPW; s++) {
                    const u64 xd = pk(xv[s][d], xv[s][d]);
                    acc[s][0] = fma2(xd, w01.x, acc[s][0]);
                    acc[s][1] = fma2(xd, w01.y, acc[s][1]);
                    acc[s][2] = fma2(xd, w23.x, acc[s][2]);
                    acc[s][3] = fma2(xd, w23.y, acc[s][3]);
                    acc[s][4] = fma2(xd, w4,    acc[s][4]);
                }
            }

            #pragma unroll
            for (int s = 0; s < SPW; s++) {
                u64* r = (s == 0) ? r0 : (s == 1) ? r1 : r2;
                if (pr == 1) {               // K at [0..4], aug hi = mterm
                    float lo, hi; unpk(acc[s][4], lo, hi);
                    *(ulonglong2*)(r + 0) = make_ulonglong2(acc[s][0], acc[s][1]);
                    *(ulonglong2*)(r + 2) = make_ulonglong2(acc[s][2], acc[s][3]);
                    r[4] = pk(lo, mterm);
                } else if (pr == 2) {        // V at [5..9], hi of [9] is 0
                    r[5] = acc[s][0];
                    *(ulonglong2*)(r + 6) = make_ulonglong2(acc[s][1], acc[s][2]);
                    *(ulonglong2*)(r + 8) = make_ulonglong2(acc[s][3], acc[s][4]);
                } else {                     // Q at [10..14], hi of [14] is 1
                    *(ulonglong2*)(r + 10) = make_ulonglong2(acc[s][0], acc[s][1]);
                    *(ulonglong2*)(r + 12) = make_ulonglong2(acc[s][2], acc[s][3]);
                    r[14] = acc[s][4];
                }
            }
        }
    }
    __syncwarp();

    // ---- phase 2: 27 lanes = 3 samples x 9 lanes; 3 q-rows per lane ----
    if (lane < 27) {
        const int sel = lane / 9;
        const int idx = lane % 9;
        const int base_row = 3 * idx;        // rows base..base+2, clamp at 24

        u64 q[3][5];
        #pragma unroll
        for (int s = 0; s < 3; s++) {
            const int row = (base_row + s < NQ) ? base_row + s : NQ - 1;
            const u64* r = &sKV[warp][sel][row][0];
            const ulonglong2 q01 = *(const ulonglong2*)(r + 10);
            const ulonglong2 q23 = *(const ulonglong2*)(r + 12);
            q[s][0] = q01.x; q[s][1] = q01.y;
            q[s][2] = q23.x; q[s][3] = q23.y;
            q[s][4] = r[14];
        }

        u64 o[3][5];
        float sum[3] = {0.f, 0.f, 0.f};
        #pragma unroll
        for (int s = 0; s < 3; s++)
            #pragma unroll
            for (int p = 0; p < 5; p++) o[s][p] = 0;

        const u64* base = &sKV[warp][sel][0][0];
        #pragma unroll
        for (int j = 0; j < NQ; j++) {
            const u64* r = base + j * RSTRIDE;
            const ulonglong2 L0 = *(const ulonglong2*)(r + 0);  // (k0k1)(k2k3)
            const ulonglong2 L1 = *(const ulonglong2*)(r + 2);  // (k4k5)(k6k7)
            const ulonglong2 L2 = *(const ulonglong2*)(r + 4);  // (k8,m)(v0v1)
            const ulonglong2 L3 = *(const ulonglong2*)(r + 6);  // (v2v3)(v4v5)
            const ulonglong2 L4 = *(const ulonglong2*)(r + 8);  // (v6v7)(v8,0)
            u64 ep[3];
            #pragma unroll
            for (int s = 0; s < 3; s++) {
                u64 acc = mul2(q[s][0], L0.x);
                acc = fma2(q[s][1], L0.y, acc);
                acc = fma2(q[s][2], L1.x, acc);
                acc = fma2(q[s][3], L1.y, acc);
                acc = fma2(q[s][4], L2.x, acc);
                float lo, hi; unpk(acc, lo, hi);
                const float e = __expf(lo + hi);
                sum[s] += e;
                ep[s] = pk(e, e);
            }
            #pragma unroll
            for (int s = 0; s < 3; s++) {
                o[s][0] = fma2(ep[s], L2.y, o[s][0]);
                o[s][1] = fma2(ep[s], L3.x, o[s][1]);
                o[s][2] = fma2(ep[s], L3.y, o[s][2]);
                o[s][3] = fma2(ep[s], L4.x, o[s][3]);
                o[s][4] = fma2(ep[s], L4.y, o[s][4]);
            }
        }

        // ---- epilogue per q-row (skip clamped duplicates) ----
        const u64 g01 = sG[0], g1p = sG[1], g2p = sG[2], g3p = sG[3];
        const u64 b01 = sBt[0], b1p = sBt[1], b2p = sBt[2], b3p = sBt[3];
        float g8, b8, zz;
        unpk(sG[4], g8, zz); unpk(sBt[4], b8, zz);
        #pragma unroll
        for (int s = 0; s < 3; s++) {
            if (s > 0 && base_row + s >= NQ) break;
            const int row = base_row + s;
            float xr[KVD];
            #pragma unroll
            for (int d = 0; d < KVD; d++) xr[d] = sX[warp][sel][row * KVD + d];

            const float inv = 1.0f / sum[s];
            const u64 inv2 = pk(inv, inv);
            const u64 f0 = fma2(o[s][0], inv2, pk(xr[0], xr[1]));
            const u64 f1 = fma2(o[s][1], inv2, pk(xr[2], xr[3]));
            const u64 f2 = fma2(o[s][2], inv2, pk(xr[4], xr[5]));
            const u64 f3 = fma2(o[s][3], inv2, pk(xr[6], xr[7]));
            const u64 f4 = fma2(o[s][4], inv2, pk(xr[8], 0.f));

            float e0,e1,e2,e3,e4,e5,e6,e7,e8,ez;
            unpk(f0, e0, e1); unpk(f1, e2, e3);
            unpk(f2, e4, e5); unpk(f3, e6, e7);
            unpk(f4, e8, ez);
            const float mu = (e0+e1+e2+e3+e4+e5+e6+e7+e8) * (1.0f/9.0f);
            const u64 nmu2 = pk(-mu, -mu);
            const u64 t0 = add2(f0, nmu2);
            const u64 t1 = add2(f1, nmu2);
            const u64 t2 = add2(f2, nmu2);
            const u64 t3 = add2(f3, nmu2);
            const float t8 = e8 - mu;
            u64 vacc = mul2(t0, t0);
            vacc = fma2(t1, t1, vacc);
            vacc = fma2(t2, t2, vacc);
            vacc = fma2(t3, t3, vacc);
            float va0, va1; unpk(vacc, va0, va1);
            const float var = (va0 + va1 + t8 * t8) * (1.0f/9.0f);
            const float rinv = rsqrtf(var + 1e-5f);
            const u64 rinv2 = pk(rinv, rinv);

            const u64 r0p = fma2(mul2(t0, rinv2), g01, b01);
            const u64 r1p = fma2(mul2(t1, rinv2), g1p, b1p);
            const u64 r2p = fma2(mul2(t2, rinv2), g2p, b2p);
            const u64 r3p = fma2(mul2(t3, rinv2), g3p, b3p);
            const float r8v = t8 * rinv * g8 + b8;

            float w0,w1,w2,w3,w4,w5,w6,w7;
            unpk(r0p,w0,w1); unpk(r1p,w2,w3); unpk(r2p,w4,w5); unpk(r3p,w6,w7);
            float* so = &sX[warp][sel][row * KVD];
            so[0]=w0; so[1]=w1; so[2]=w2; so[3]=w3;
            so[4]=w4; so[5]=w5; so[6]=w6; so[7]=w7; so[8]=r8v;
        }
    }
    __syncwarp();

    // ---- coalesced output ----
    {
        float* orow = out + s0 * ROW;
        const int total = cnt * ROW;
        for (int i = lane; i < total; i += 32) orow[i] = sxAll[i];
    }
}

extern "C" void kernel_launch(void* const* d_in, const int* in_sizes, int n_in,
                              void* d_out, int out_size)
{
    const float* x     = (const float*)d_in[0];
    const float* mask  = (const float*)d_in[1];
    const float* Wq    = (const float*)d_in[2];
    const float* bq    = (const float*)d_in[3];
    const float* Wk    = (const float*)d_in[4];
    const float* bk    = (const float*)d_in[5];
    const float* Wv    = (const float*)d_in[6];
    const float* bv    = (const float*)d_in[7];
    const float* gamma = (const float*)d_in[8];
    const float* beta  = (const float*)d_in[9];
    float* out = (float*)d_out;

    const int B = in_sizes[0] / ROW;
    const int blocks = (B + SPB - 1) / SPB;
    attn_fused_kernel<<<blocks, THREADS>>>(x, mask, Wq, bq, Wk, bk, Wv, bv,
                                           gamma, beta, out, B);
}